// round 8
// baseline (speedup 1.0000x reference)
#include <cuda_runtime.h>
#include <cuda_bf16.h>
#include <cstdint>

// Problem constants
#define BATCH 4
#define SEQ   2048
#define DM    1024
#define NH    16
#define HD    64
#define M_ROWS (BATCH*SEQ)   // 8192

// Scratch (device globals; no allocation allowed)
__device__ float g_qkv[(size_t)M_ROWS * 3 * DM];   // [B*T, 3*C] (sel, head, hd)
__device__ float g_y[(size_t)M_ROWS * DM];         // [B*T, C]

__device__ __forceinline__ uint32_t f2tf(float f) {
    uint32_t u;
    asm("cvt.rna.tf32.f32 %0, %1;" : "=r"(u) : "f"(f));
    return u;
}

__device__ __forceinline__ uint32_t smem_u32(const void* p) {
    uint32_t a;
    asm("{ .reg .u64 t; cvta.to.shared.u64 t, %1; cvt.u32.u64 %0, t; }"
        : "=r"(a) : "l"(p));
    return a;
}

__device__ __forceinline__ void cp16(uint32_t dst, const void* src) {
    asm volatile("cp.async.ca.shared.global [%0], [%1], 16;" :: "r"(dst), "l"(src));
}
#define CP_COMMIT() asm volatile("cp.async.commit_group;" ::: "memory")
#define CP_WAIT(n)  asm volatile("cp.async.wait_group %0;" :: "n"(n) : "memory")

#define MMA_TF32(acc, a, b0v, b1v)                                              \
    asm volatile(                                                               \
        "mma.sync.aligned.m16n8k8.row.col.f32.tf32.tf32.f32 "                   \
        "{%0,%1,%2,%3}, {%4,%5,%6,%7}, {%8,%9}, {%0,%1,%2,%3};"                 \
        : "+f"(acc[0]), "+f"(acc[1]), "+f"(acc[2]), "+f"(acc[3])                \
        : "r"(a[0]), "r"(a[1]), "r"(a[2]), "r"(a[3]), "r"(b0v), "r"(b1v))

// ---------------------------------------------------------------------------
// TF32 GEMM with bias: C[M,N] = A[M,K] @ B[K,N] + bias[N]
// 128x128 block tile, BK=16 double-buffered via cp.async, 128 thr (4 warps 2x2),
// warp tile 64x64 (4x8 grid of m16n8k8). fp32 staged in smem; tf32 cvt at
// fragment load. A smem [row][k] stride 20 (conflict-free quad pattern),
// B smem [k][n] stride 136.
// ---------------------------------------------------------------------------
#define AST 20
#define BST 136

__global__ __launch_bounds__(128) void tf32_gemm_bias(
    const float* __restrict__ A, const float* __restrict__ B,
    const float* __restrict__ bias, float* __restrict__ C,
    int M, int N, int K)
{
    __shared__ float As[2][128][AST];   // 2*128*20*4 = 20480 B
    __shared__ float Bs[2][16][BST];    // 2*16*136*4 = 17408 B

    const int tid  = threadIdx.x;
    const int lane = tid & 31;
    const int wid  = tid >> 5;
    const int gid  = lane >> 2;
    const int tig  = lane & 3;
    const int wm   = (wid & 1) * 64;
    const int wn   = (wid >> 1) * 64;
    const int bm   = blockIdx.y * 128;
    const int bn   = blockIdx.x * 128;

    const uint32_t aBase = smem_u32(&As[0][0][0]);
    const uint32_t bBase = smem_u32(&Bs[0][0][0]);

    // cp.async staging indices
    const uint32_t aDst0 = aBase + tid * (AST * 4);            // row tid, 4x16B chunks
    const int brow = tid >> 3;
    const int bcol = (tid & 7) * 16;
    const uint32_t bDst0 = bBase + brow * (BST * 4) + bcol * 4;

    const float* aSrc = A + (size_t)(bm + tid) * K;            // + k0 + j*4
    const float* bSrcBase = B + bn + bcol;                     // + (k0+brow)*N + j*4

    float acc[4][8][4];
#pragma unroll
    for (int mt = 0; mt < 4; mt++)
#pragma unroll
        for (int nt = 0; nt < 8; nt++)
#pragma unroll
            for (int i = 0; i < 4; i++) acc[mt][nt][i] = 0.f;

    const int NT = K / 16;

    // Preload tile 0 -> buf 0
    {
        const float* bs = bSrcBase + (size_t)brow * N;
#pragma unroll
        for (int j = 0; j < 4; j++) {
            cp16(aDst0 + j * 16, aSrc + j * 4);
            cp16(bDst0 + j * 16, bs + j * 4);
        }
    }
    CP_COMMIT();

    for (int t = 0; t < NT; t++) {
        const int buf = t & 1;
        if (t + 1 < NT) {
            const int k0 = (t + 1) * 16;
            const uint32_t nb = (t + 1) & 1;
            const float* as = aSrc + k0;
            const float* bs = bSrcBase + (size_t)(k0 + brow) * N;
            const uint32_t ad = aDst0 + nb * 10240;
            const uint32_t bd = bDst0 + nb * 8704;
#pragma unroll
            for (int j = 0; j < 4; j++) {
                cp16(ad + j * 16, as + j * 4);
                cp16(bd + j * 16, bs + j * 4);
            }
            CP_COMMIT();
            CP_WAIT(1);
        } else {
            CP_WAIT(0);
        }
        __syncthreads();

#pragma unroll
        for (int kk = 0; kk < 16; kk += 8) {
            uint32_t af[4][4], bf[8][2];
#pragma unroll
            for (int mt = 0; mt < 4; mt++) {
                const int r = wm + mt * 16 + gid;
                af[mt][0] = f2tf(As[buf][r]    [kk + tig]);
                af[mt][1] = f2tf(As[buf][r + 8][kk + tig]);
                af[mt][2] = f2tf(As[buf][r]    [kk + tig + 4]);
                af[mt][3] = f2tf(As[buf][r + 8][kk + tig + 4]);
            }
#pragma unroll
            for (int nt = 0; nt < 8; nt++) {
                const int c = wn + nt * 8 + gid;
                bf[nt][0] = f2tf(Bs[buf][kk + tig]    [c]);
                bf[nt][1] = f2tf(Bs[buf][kk + tig + 4][c]);
            }
#pragma unroll
            for (int mt = 0; mt < 4; mt++)
#pragma unroll
                for (int nt = 0; nt < 8; nt++)
                    MMA_TF32(acc[mt][nt], af[mt], bf[nt][0], bf[nt][1]);
        }
        __syncthreads();
    }

    // Epilogue with bias
#pragma unroll
    for (int mt = 0; mt < 4; mt++) {
        const int r0 = bm + wm + mt * 16 + gid;
#pragma unroll
        for (int nt = 0; nt < 8; nt++) {
            const int col = bn + wn + nt * 8 + 2 * tig;
            const float bx = bias[col], by = bias[col + 1];
            float2 v0 = {acc[mt][nt][0] + bx, acc[mt][nt][1] + by};
            float2 v1 = {acc[mt][nt][2] + bx, acc[mt][nt][3] + by};
            *(float2*)(C + (size_t)r0 * N + col)       = v0;
            *(float2*)(C + (size_t)(r0 + 8) * N + col) = v1;
        }
    }
}

// ---------------------------------------------------------------------------
// Tensor-core flash attention: 128 queries/block, 4 warps x 32 queries.
// B-fragments (K and V) shared across each warp's 2 query sub-tiles.
// P reuses S's registers (bit-cast in place). grid = (T/128, H, B), block=128.
// ---------------------------------------------------------------------------
__global__ __launch_bounds__(128) void flash_attn_tc(
    const float* __restrict__ qkv, float* __restrict__ y)
{
    __shared__ uint32_t ks[64][68];
    __shared__ uint32_t vst[64][68];

    const int tid  = threadIdx.x;
    const int lane = tid & 31;
    const int wid  = tid >> 5;
    const int gid  = lane >> 2;
    const int tig  = lane & 3;
    const int wq   = wid * 32;
    const int qt0  = (int)(gridDim.x - 1 - blockIdx.x) * 128;  // heavy tiles first
    const int h    = blockIdx.y;
    const int b    = blockIdx.z;

    // Q fragments (scale folded); qf[mt][kk][4]
    uint32_t qf[2][8][4];
#pragma unroll
    for (int mt = 0; mt < 2; mt++) {
        const float* q0 = qkv + ((size_t)(b * SEQ + qt0 + wq + mt * 16 + gid) * (3 * DM)) + h * HD;
        const float* q1 = q0 + (size_t)8 * 3 * DM;
#pragma unroll
        for (int kk = 0; kk < 8; kk++) {
            qf[mt][kk][0] = f2tf(q0[kk * 8 + tig]     * 0.125f);
            qf[mt][kk][1] = f2tf(q1[kk * 8 + tig]     * 0.125f);
            qf[mt][kk][2] = f2tf(q0[kk * 8 + tig + 4] * 0.125f);
            qf[mt][kk][3] = f2tf(q1[kk * 8 + tig + 4] * 0.125f);
        }
    }

    float o[2][8][4];
#pragma unroll
    for (int mt = 0; mt < 2; mt++)
#pragma unroll
        for (int nt = 0; nt < 8; nt++) {
            o[mt][nt][0] = 0.f; o[mt][nt][1] = 0.f;
            o[mt][nt][2] = 0.f; o[mt][nt][3] = 0.f;
        }
    float m[2][2] = {{-1e30f, -1e30f}, {-1e30f, -1e30f}};
    float l[2][2] = {{0.f, 0.f}, {0.f, 0.f}};

    const int ntiles = qt0 / 64 + 2;
    const int krow = tid & 63;
    const int kcb  = (tid >> 6) * 32;

    const int src0 = tig >> 1;
    const int src2 = (tig >> 1) + 2;
    const bool sel = (tig & 1);

    for (int kt = 0; kt < ntiles; kt++) {
        const int kt0 = kt * 64;

        __syncthreads();
        {
            const float* kp = qkv + ((size_t)(b * SEQ + kt0 + krow) * (3 * DM)) + DM + h * HD + kcb;
            const float* vp = kp + DM;
#pragma unroll
            for (int j = 0; j < 32; j += 4) {
                float4 k4 = *(const float4*)(kp + j);
                float4 v4 = *(const float4*)(vp + j);
                uint4 w;
                w.x = f2tf(k4.x); w.y = f2tf(k4.y); w.z = f2tf(k4.z); w.w = f2tf(k4.w);
                *(uint4*)&ks[krow][kcb + j] = w;
                vst[kcb + j + 0][krow] = f2tf(v4.x);
                vst[kcb + j + 1][krow] = f2tf(v4.y);
                vst[kcb + j + 2][krow] = f2tf(v4.z);
                vst[kcb + j + 3][krow] = f2tf(v4.w);
            }
        }
        __syncthreads();

        if (kt0 > qt0 + wq + 31) continue;   // whole warp masked

        // S = Q K^T (warp: 32 rows x 64 keys; B frags shared across mt)
        float acc[2][8][4];
#pragma unroll
        for (int mt = 0; mt < 2; mt++)
#pragma unroll
            for (int nt = 0; nt < 8; nt++) {
                acc[mt][nt][0] = 0.f; acc[mt][nt][1] = 0.f;
                acc[mt][nt][2] = 0.f; acc[mt][nt][3] = 0.f;
            }
#pragma unroll
        for (int kk = 0; kk < 8; kk++) {
            uint32_t bf0[8], bf1[8];
#pragma unroll
            for (int nt = 0; nt < 8; nt++) {
                bf0[nt] = ks[nt * 8 + gid][kk * 8 + tig];
                bf1[nt] = ks[nt * 8 + gid][kk * 8 + tig + 4];
            }
#pragma unroll
            for (int mt = 0; mt < 2; mt++)
#pragma unroll
                for (int nt = 0; nt < 8; nt++)
                    MMA_TF32(acc[mt][nt], qf[mt][kk], bf0[nt], bf1[nt]);
        }

        // Causal mask
#pragma unroll
        for (int mt = 0; mt < 2; mt++) {
            if (kt0 + 63 > qt0 + wq + mt * 16) {
                const int r0 = qt0 + wq + mt * 16 + gid, r1 = r0 + 8;
#pragma unroll
                for (int nt = 0; nt < 8; nt++) {
                    const int c = kt0 + nt * 8 + 2 * tig;
                    if (c     > r0) acc[mt][nt][0] = -1e30f;
                    if (c + 1 > r0) acc[mt][nt][1] = -1e30f;
                    if (c     > r1) acc[mt][nt][2] = -1e30f;
                    if (c + 1 > r1) acc[mt][nt][3] = -1e30f;
                }
            }
        }

        // Online softmax per mt; P written in place over acc (bit-cast tf32)
#pragma unroll
        for (int mt = 0; mt < 2; mt++) {
            float mt0 = -1e30f, mt1 = -1e30f;
#pragma unroll
            for (int nt = 0; nt < 8; nt++) {
                mt0 = fmaxf(mt0, fmaxf(acc[mt][nt][0], acc[mt][nt][1]));
                mt1 = fmaxf(mt1, fmaxf(acc[mt][nt][2], acc[mt][nt][3]));
            }
            mt0 = fmaxf(mt0, __shfl_xor_sync(0xffffffffu, mt0, 1));
            mt0 = fmaxf(mt0, __shfl_xor_sync(0xffffffffu, mt0, 2));
            mt1 = fmaxf(mt1, __shfl_xor_sync(0xffffffffu, mt1, 1));
            mt1 = fmaxf(mt1, __shfl_xor_sync(0xffffffffu, mt1, 2));

            const float mn0 = fmaxf(m[mt][0], mt0), mn1 = fmaxf(m[mt][1], mt1);
            const float cr0 = __expf(m[mt][0] - mn0), cr1 = __expf(m[mt][1] - mn1);
            m[mt][0] = mn0; m[mt][1] = mn1;
            l[mt][0] *= cr0; l[mt][1] *= cr1;

            float s0 = 0.f, s1 = 0.f;
#pragma unroll
            for (int nt = 0; nt < 8; nt++) {
                const float p0 = __expf(acc[mt][nt][0] - mn0);
                const float p1 = __expf(acc[mt][nt][1] - mn0);
                const float p2 = __expf(acc[mt][nt][2] - mn1);
                const float p3 = __expf(acc[mt][nt][3] - mn1);
                s0 += p0 + p1;
                s1 += p2 + p3;
                o[mt][nt][0] *= cr0; o[mt][nt][1] *= cr0;
                o[mt][nt][2] *= cr1; o[mt][nt][3] *= cr1;
                acc[mt][nt][0] = __uint_as_float(f2tf(p0));
                acc[mt][nt][1] = __uint_as_float(f2tf(p1));
                acc[mt][nt][2] = __uint_as_float(f2tf(p2));
                acc[mt][nt][3] = __uint_as_float(f2tf(p3));
            }
            s0 += __shfl_xor_sync(0xffffffffu, s0, 1);
            s0 += __shfl_xor_sync(0xffffffffu, s0, 2);
            s1 += __shfl_xor_sync(0xffffffffu, s1, 1);
            s1 += __shfl_xor_sync(0xffffffffu, s1, 2);
            l[mt][0] += s0; l[mt][1] += s1;
        }

        // O += P V : A-frags via width-4 quad shfl; V frags shared across mt
#pragma unroll
        for (int kk = 0; kk < 8; kk++) {
            uint32_t pa[2][4];
#pragma unroll
            for (int mt = 0; mt < 2; mt++) {
                const uint32_t e0 = __float_as_uint(acc[mt][kk][0]);
                const uint32_t e1 = __float_as_uint(acc[mt][kk][1]);
                const uint32_t e2 = __float_as_uint(acc[mt][kk][2]);
                const uint32_t e3 = __float_as_uint(acc[mt][kk][3]);
                const uint32_t u0 = __shfl_sync(0xffffffffu, e0, src0, 4);
                const uint32_t u1 = __shfl_sync(0xffffffffu, e1, src0, 4);
                pa[mt][0] = sel ? u1 : u0;
                const uint32_t v0 = __shfl_sync(0xffffffffu, e2, src0, 4);
                const uint32_t v1 = __shfl_sync(0xffffffffu, e3, src0, 4);
                pa[mt][1] = sel ? v1 : v0;
                const uint32_t w0 = __shfl_sync(0xffffffffu, e0, src2, 4);
                const uint32_t w1 = __shfl_sync(0xffffffffu, e1, src2, 4);
                pa[mt][2] = sel ? w1 : w0;
                const uint32_t x0 = __shfl_sync(0xffffffffu, e2, src2, 4);
                const uint32_t x1 = __shfl_sync(0xffffffffu, e3, src2, 4);
                pa[mt][3] = sel ? x1 : x0;
            }
#pragma unroll
            for (int nt = 0; nt < 8; nt++) {
                const uint32_t b0 = vst[nt * 8 + gid][kk * 8 + tig];
                const uint32_t b1 = vst[nt * 8 + gid][kk * 8 + tig + 4];
#pragma unroll
                for (int mt = 0; mt < 2; mt++)
                    MMA_TF32(o[mt][nt], pa[mt], b0, b1);
            }
        }
    }

    // Epilogue: normalize and write y [B*T, DM]
#pragma unroll
    for (int mt = 0; mt < 2; mt++) {
        const float i0 = 1.f / l[mt][0], i1 = 1.f / l[mt][1];
        float* y0 = y + (size_t)(b * SEQ + qt0 + wq + mt * 16 + gid) * DM + h * HD;
        float* y1 = y0 + (size_t)8 * DM;
#pragma unroll
        for (int nt = 0; nt < 8; nt++) {
            const int c = nt * 8 + 2 * tig;
            float2 w0 = {o[mt][nt][0] * i0, o[mt][nt][1] * i0};
            float2 w1 = {o[mt][nt][2] * i1, o[mt][nt][3] * i1};
            *(float2*)(y0 + c) = w0;
            *(float2*)(y1 + c) = w1;
        }
    }
}

// ---------------------------------------------------------------------------
// Launch
// ---------------------------------------------------------------------------
extern "C" void kernel_launch(void* const* d_in, const int* in_sizes, int n_in,
                              void* d_out, int out_size)
{
    (void)in_sizes; (void)n_in; (void)out_size;
    const float* x      = (const float*)d_in[0];
    const float* w_qkv  = (const float*)d_in[1];
    const float* b_qkv  = (const float*)d_in[2];
    const float* w_proj = (const float*)d_in[3];
    const float* b_proj = (const float*)d_in[4];
    float* out = (float*)d_out;

    float* qkv = nullptr;
    float* y   = nullptr;
    cudaGetSymbolAddress((void**)&qkv, g_qkv);
    cudaGetSymbolAddress((void**)&y,   g_y);

    // 1) QKV projection: [8192,1024] @ [1024,3072] + b
    tf32_gemm_bias<<<dim3(3 * DM / 128, M_ROWS / 128), 128>>>(
        x, w_qkv, b_qkv, qkv, M_ROWS, 3 * DM, DM);

    // 2) Causal flash attention (128 queries per block, 4 warps)
    flash_attn_tc<<<dim3(SEQ / 128, NH, BATCH), 128>>>(qkv, y);

    // 3) Output projection: [8192,1024] @ [1024,1024] + b
    tf32_gemm_bias<<<dim3(DM / 128, M_ROWS / 128), 128>>>(
        y, w_proj, b_proj, out, M_ROWS, DM, DM);
}